// round 16
// baseline (speedup 1.0000x reference)
#include <cuda_runtime.h>
#include <cuda_bf16.h>
#include <math.h>
#include <stdint.h>

// Problem constants
#define BB 1024
#define CC 512
#define DD 256
#define KK 8192
#define HH 512
#define G3 1536
#define TT 8
#define HW 49

// ---------------- scratch layout ----------------
#define OFF_PREV    0
#define OFF_H       262144
#define OFF_GX      786432
#define OFF_GH      2359296
#define OFF_WGB     4980736
#define OFF_BGB     5505024
#define OFF_Z1      6029312
#define OFF_Z       6553600
#define OFF_SM      6815744
#define OFF_CB      7340032
#define OFF_EW      9437184
#define OFF_DW      11534336
#define OFF_CS      13631488
#define OFF_COUNTS  13647872
#define OFF_CBSQ    13656064
#define OFF_ZZ      13664256
#define OFF_LOSS    13665313
#define OFF_DMIN    13665316
#define G_TOTAL     13667368

#define OFF_GB OFF_GX

__device__ float g_buf[G_TOTAL];

// output layout
#define OUT_H     0
#define OUT_CODES 524288
#define OUT_IDX   2621440
#define OUT_ZC    2629632
#define OUT_LOSS  4726784

typedef unsigned long long ull;

// ---------------- helpers ----------------
__device__ __forceinline__ float sigf(float x) { return 1.0f / (1.0f + expf(-x)); }

__device__ __forceinline__ unsigned fenc(float f) {
    unsigned u = __float_as_uint(f);
    return (u & 0x80000000u) ? ~u : (u | 0x80000000u);
}

__device__ __forceinline__ ull dup2(float x) {
    ull r; asm("mov.b64 %0,{%1,%1};" : "=l"(r) : "f"(x)); return r;
}
__device__ __forceinline__ void fma2(ull& acc, ull a, ull b) {
    asm("fma.rn.f32x2 %0,%1,%2,%0;" : "+l"(acc) : "l"(a), "l"(b));
}
__device__ __forceinline__ float2 unp(ull v) {
    float2 f; asm("mov.b64 {%0,%1},%2;" : "=f"(f.x), "=f"(f.y) : "l"(v)); return f;
}

// ---------------- init ----------------
__global__ void init_copy(const float* __restrict__ cb_in,
                          const float* __restrict__ cs_in,
                          const float* __restrict__ ew_in) {
    int i = blockIdx.x * blockDim.x + threadIdx.x;
    if (i < KK * DD) {
        g_buf[OFF_CB + i] = cb_in[i];
        g_buf[OFF_EW + i] = ew_in[i];
    }
    if (i < KK) g_buf[OFF_CS + i] = cs_in[i];
}

__global__ void init_state(const float* __restrict__ bos) {
    int i = blockIdx.x * blockDim.x + threadIdx.x;
    if (i < BB * DD) g_buf[OFF_PREV + i] = bos[i & (DD - 1)];
    if (i < BB * HH) g_buf[OFF_H + i] = 0.0f;
    if (i < BB) {
        ((ull*)(g_buf + OFF_DMIN))[i] = 0xFFFFFFFFFFFFFFFFULL;
        g_buf[OFF_ZZ + i] = 0.0f;
    }
    if (i == 0) g_buf[OFF_LOSS] = 0.0f;
}

__global__ void packw(const float* __restrict__ Wg, const float* __restrict__ bg,
                      const float* __restrict__ Wb, const float* __restrict__ bbp) {
    int i = blockIdx.x * blockDim.x + threadIdx.x;
    if (i < CC * HH) {
        g_buf[OFF_WGB + i] = Wg[i];
        g_buf[OFF_WGB + CC * HH + i] = Wb[i];
    }
    if (i < CC) {
        g_buf[OFF_BGB + i] = bg[i];
        g_buf[OFF_BGB + CC + i] = bbp[i];
    }
}

__global__ void cbsq_init() {
    int k = blockIdx.x, d = threadIdx.x;
    float v = g_buf[OFF_CB + k * DD + d];
    __shared__ float s[256];
    s[d] = __fmul_rn(v, v);
    __syncthreads();
    #pragma unroll
    for (int o = 128; o; o >>= 1) {
        if (d < o) s[d] = __fadd_rn(s[d], s[d + o]);
        __syncthreads();
    }
    if (d == 0) g_buf[OFF_CBSQ + k] = s[0];
}

// ---------------- spatial mean: warp per 4 channels ----------------
__global__ void smean_kernel(const float* __restrict__ sf) {
    int w = (blockIdx.x * blockDim.x + threadIdx.x) >> 5;
    int lane = threadIdx.x & 31;
    if (w >= BB * CC / 4) return;
    const float* p = sf + (size_t)w * 4 * HW;
    float s[4];
    #pragma unroll
    for (int c = 0; c < 4; c++) {
        s[c] = p[c * HW + lane];
        if (lane + 32 < HW) s[c] = __fadd_rn(s[c], p[c * HW + lane + 32]);
    }
    #pragma unroll
    for (int c = 0; c < 4; c++) {
        #pragma unroll
        for (int o = 16; o; o >>= 1) s[c] = __fadd_rn(s[c], __shfl_down_sync(0xffffffffu, s[c], o));
        if (lane == 0) g_buf[OFF_SM + w * 4 + c] = s[c] / 49.0f;
    }
}

// =====================================================================
#define BIGP (128 + 4)

// ---------------- GRU dual GEMM (BK=16) ----------------
__global__ __launch_bounds__(256, 2) void gru_gemm(
    const float* __restrict__ W_ih, const float* __restrict__ b_ih,
    const float* __restrict__ W_hh, const float* __restrict__ b_hh) {
    __shared__ __align__(16) float As[2][16][BIGP];
    __shared__ __align__(16) float Bs[2][16][BIGP];
    const float* A; const float* W; const float* bias; float* out; int K;
    if (blockIdx.z == 0) { A = g_buf + OFF_PREV; W = W_ih; bias = b_ih; out = g_buf + OFF_GX; K = DD; }
    else                 { A = g_buf + OFF_H;    W = W_hh; bias = b_hh; out = g_buf + OFF_GH; K = HH; }

    int tid = threadIdx.x, tx = tid & 15, ty = tid >> 4;
    int m0 = blockIdx.y * 128, n0 = blockIdx.x * 128;
    int lr = tid >> 1, lc = (tid & 1) * 8;
    const float* Ap = A + (size_t)(m0 + lr) * K + lc;
    const float* Wp = W + (size_t)(n0 + lr) * K + lc;

    ull acc[4][8];
    #pragma unroll
    for (int i = 0; i < 4; i++)
        #pragma unroll
        for (int j = 0; j < 8; j++) acc[i][j] = 0ull;

    {
        float4 a0 = *(const float4*)Ap;
        float4 a1 = *(const float4*)(Ap + 4);
        float4 b0 = *(const float4*)Wp;
        float4 b1 = *(const float4*)(Wp + 4);
        As[0][lc + 0][lr] = a0.x; As[0][lc + 1][lr] = a0.y; As[0][lc + 2][lr] = a0.z; As[0][lc + 3][lr] = a0.w;
        As[0][lc + 4][lr] = a1.x; As[0][lc + 5][lr] = a1.y; As[0][lc + 6][lr] = a1.z; As[0][lc + 7][lr] = a1.w;
        Bs[0][lc + 0][lr] = b0.x; Bs[0][lc + 1][lr] = b0.y; Bs[0][lc + 2][lr] = b0.z; Bs[0][lc + 3][lr] = b0.w;
        Bs[0][lc + 4][lr] = b1.x; Bs[0][lc + 5][lr] = b1.y; Bs[0][lc + 6][lr] = b1.z; Bs[0][lc + 7][lr] = b1.w;
    }
    __syncthreads();

    int nk = K >> 4;
    for (int ko = 0; ko < nk; ko++) {
        int cur = ko & 1, nxt = cur ^ 1;
        float4 qa0, qa1, qb0, qb1;
        if (ko + 1 < nk) {
            qa0 = *(const float4*)(Ap + (ko + 1) * 16);
            qa1 = *(const float4*)(Ap + (ko + 1) * 16 + 4);
            qb0 = *(const float4*)(Wp + (ko + 1) * 16);
            qb1 = *(const float4*)(Wp + (ko + 1) * 16 + 4);
        }
        #pragma unroll
        for (int kk = 0; kk < 16; kk++) {
            ulonglong2 a01 = *(const ulonglong2*)&As[cur][kk][ty * 8];
            ulonglong2 a23 = *(const ulonglong2*)&As[cur][kk][ty * 8 + 4];
            float4 b0 = *(const float4*)&Bs[cur][kk][tx * 8];
            float4 b1 = *(const float4*)&Bs[cur][kk][tx * 8 + 4];
            ull aa[4] = {a01.x, a01.y, a23.x, a23.y};
            ull bb[8] = {dup2(b0.x), dup2(b0.y), dup2(b0.z), dup2(b0.w),
                         dup2(b1.x), dup2(b1.y), dup2(b1.z), dup2(b1.w)};
            #pragma unroll
            for (int i = 0; i < 4; i++)
                #pragma unroll
                for (int j = 0; j < 8; j++) fma2(acc[i][j], aa[i], bb[j]);
        }
        if (ko + 1 < nk) {
            As[nxt][lc + 0][lr] = qa0.x; As[nxt][lc + 1][lr] = qa0.y; As[nxt][lc + 2][lr] = qa0.z; As[nxt][lc + 3][lr] = qa0.w;
            As[nxt][lc + 4][lr] = qa1.x; As[nxt][lc + 5][lr] = qa1.y; As[nxt][lc + 6][lr] = qa1.z; As[nxt][lc + 7][lr] = qa1.w;
            Bs[nxt][lc + 0][lr] = qb0.x; Bs[nxt][lc + 1][lr] = qb0.y; Bs[nxt][lc + 2][lr] = qb0.z; Bs[nxt][lc + 3][lr] = qb0.w;
            Bs[nxt][lc + 4][lr] = qb1.x; Bs[nxt][lc + 5][lr] = qb1.y; Bs[nxt][lc + 6][lr] = qb1.z; Bs[nxt][lc + 7][lr] = qb1.w;
        }
        __syncthreads();
    }

    float bv[8];
    #pragma unroll
    for (int j = 0; j < 8; j++) bv[j] = bias[n0 + tx * 8 + j];
    #pragma unroll
    for (int i = 0; i < 4; i++) {
        float r0[8], r1[8];
        #pragma unroll
        for (int j = 0; j < 8; j++) {
            float2 v = unp(acc[i][j]);
            r0[j] = __fadd_rn(v.x, bv[j]);
            r1[j] = __fadd_rn(v.y, bv[j]);
        }
        size_t base0 = (size_t)(m0 + ty * 8 + 2 * i) * G3 + n0 + tx * 8;
        size_t base1 = base0 + G3;
        *(float4*)&out[base0]     = make_float4(r0[0], r0[1], r0[2], r0[3]);
        *(float4*)&out[base0 + 4] = make_float4(r0[4], r0[5], r0[6], r0[7]);
        *(float4*)&out[base1]     = make_float4(r1[0], r1[1], r1[2], r1[3]);
        *(float4*)&out[base1 + 4] = make_float4(r1[4], r1[5], r1[6], r1[7]);
    }
}

// ---------------- VQ GEMM (BK=16) + fused distance/argmin ----------------
__global__ __launch_bounds__(256, 2) void vq_gemm() {
    __shared__ __align__(16) float As[2][16][BIGP];
    __shared__ __align__(16) float Bs[2][16][BIGP];
    const float* A = g_buf + OFF_Z;
    const float* W = g_buf + OFF_CB;
    const int K = DD;

    int tid = threadIdx.x, tx = tid & 15, ty = tid >> 4;
    int m0 = blockIdx.y * 128, n0 = blockIdx.x * 128;
    int lr = tid >> 1, lc = (tid & 1) * 8;
    const float* Ap = A + (size_t)(m0 + lr) * K + lc;
    const float* Wp = W + (size_t)(n0 + lr) * K + lc;

    ull acc[4][8];
    #pragma unroll
    for (int i = 0; i < 4; i++)
        #pragma unroll
        for (int j = 0; j < 8; j++) acc[i][j] = 0ull;

    {
        float4 a0 = *(const float4*)Ap;
        float4 a1 = *(const float4*)(Ap + 4);
        float4 b0 = *(const float4*)Wp;
        float4 b1 = *(const float4*)(Wp + 4);
        As[0][lc + 0][lr] = a0.x; As[0][lc + 1][lr] = a0.y; As[0][lc + 2][lr] = a0.z; As[0][lc + 3][lr] = a0.w;
        As[0][lc + 4][lr] = a1.x; As[0][lc + 5][lr] = a1.y; As[0][lc + 6][lr] = a1.z; As[0][lc + 7][lr] = a1.w;
        Bs[0][lc + 0][lr] = b0.x; Bs[0][lc + 1][lr] = b0.y; Bs[0][lc + 2][lr] = b0.z; Bs[0][lc + 3][lr] = b0.w;
        Bs[0][lc + 4][lr] = b1.x; Bs[0][lc + 5][lr] = b1.y; Bs[0][lc + 6][lr] = b1.z; Bs[0][lc + 7][lr] = b1.w;
    }
    __syncthreads();

    const int nk = K >> 4;
    for (int ko = 0; ko < nk; ko++) {
        int cur = ko & 1, nxt = cur ^ 1;
        float4 qa0, qa1, qb0, qb1;
        if (ko + 1 < nk) {
            qa0 = *(const float4*)(Ap + (ko + 1) * 16);
            qa1 = *(const float4*)(Ap + (ko + 1) * 16 + 4);
            qb0 = *(const float4*)(Wp + (ko + 1) * 16);
            qb1 = *(const float4*)(Wp + (ko + 1) * 16 + 4);
        }
        #pragma unroll
        for (int kk = 0; kk < 16; kk++) {
            ulonglong2 a01 = *(const ulonglong2*)&As[cur][kk][ty * 8];
            ulonglong2 a23 = *(const ulonglong2*)&As[cur][kk][ty * 8 + 4];
            float4 b0 = *(const float4*)&Bs[cur][kk][tx * 8];
            float4 b1 = *(const float4*)&Bs[cur][kk][tx * 8 + 4];
            ull aa[4] = {a01.x, a01.y, a23.x, a23.y};
            ull bb[8] = {dup2(b0.x), dup2(b0.y), dup2(b0.z), dup2(b0.w),
                         dup2(b1.x), dup2(b1.y), dup2(b1.z), dup2(b1.w)};
            #pragma unroll
            for (int i = 0; i < 4; i++)
                #pragma unroll
                for (int j = 0; j < 8; j++) fma2(acc[i][j], aa[i], bb[j]);
        }
        if (ko + 1 < nk) {
            As[nxt][lc + 0][lr] = qa0.x; As[nxt][lc + 1][lr] = qa0.y; As[nxt][lc + 2][lr] = qa0.z; As[nxt][lc + 3][lr] = qa0.w;
            As[nxt][lc + 4][lr] = qa1.x; As[nxt][lc + 5][lr] = qa1.y; As[nxt][lc + 6][lr] = qa1.z; As[nxt][lc + 7][lr] = qa1.w;
            Bs[nxt][lc + 0][lr] = qb0.x; Bs[nxt][lc + 1][lr] = qb0.y; Bs[nxt][lc + 2][lr] = qb0.z; Bs[nxt][lc + 3][lr] = qb0.w;
            Bs[nxt][lc + 4][lr] = qb1.x; Bs[nxt][lc + 5][lr] = qb1.y; Bs[nxt][lc + 6][lr] = qb1.z; Bs[nxt][lc + 7][lr] = qb1.w;
        }
        __syncthreads();
    }

    float cq[8];
    #pragma unroll
    for (int j = 0; j < 8; j++) cq[j] = g_buf[OFF_CBSQ + n0 + tx * 8 + j];

    #pragma unroll
    for (int i = 0; i < 4; i++) {
        int m = m0 + ty * 8 + 2 * i;
        float zz0 = g_buf[OFF_ZZ + m];
        float zz1 = g_buf[OFF_ZZ + m + 1];
        ull b0 = 0xFFFFFFFFFFFFFFFFULL, b1 = 0xFFFFFFFFFFFFFFFFULL;
        #pragma unroll
        for (int j = 0; j < 8; j++) {
            unsigned n = (unsigned)(n0 + tx * 8 + j);
            float2 v = unp(acc[i][j]);
            float d0 = __fadd_rn(__fsub_rn(zz0, __fmul_rn(2.0f, v.x)), cq[j]);
            float d1 = __fadd_rn(__fsub_rn(zz1, __fmul_rn(2.0f, v.y)), cq[j]);
            ull k0 = ((ull)fenc(d0) << 32) | n;
            ull k1 = ((ull)fenc(d1) << 32) | n;
            b0 = min(b0, k0);
            b1 = min(b1, k1);
        }
        #pragma unroll
        for (int o = 1; o < 16; o <<= 1) {
            b0 = min(b0, __shfl_xor_sync(0xffffffffu, b0, o));
            b1 = min(b1, __shfl_xor_sync(0xffffffffu, b1, o));
        }
        if (tx == 0) {
            atomicMin((ull*)(g_buf + OFF_DMIN) + m,     b0);
            atomicMin((ull*)(g_buf + OFF_DMIN) + m + 1, b1);
        }
    }
}

// ---------------- MED GEMM: 64x64, BK=16, 128 threads ----------------
template <int RELU, int ZZ>
__global__ __launch_bounds__(128) void med_gemm(
    const float* __restrict__ A, const float* __restrict__ W,
    const float* __restrict__ bias, float* __restrict__ C,
    int N, int K) {
    __shared__ __align__(16) float As[2][16][68];
    __shared__ __align__(16) float Bs[2][16][68];
    __shared__ float rs[64];

    int tid = threadIdx.x, tx = tid & 15, ty = tid >> 4;
    int m0 = blockIdx.y * 64, n0 = blockIdx.x * 64;
    if (ZZ && tid < 64) rs[tid] = 0.0f;

    int f0 = tid, f1 = tid + 128;
    int r0_ = f0 >> 2, k0_ = (f0 & 3) * 4;
    int r1_ = f1 >> 2, k1_ = (f1 & 3) * 4;
    const float* Ap0 = A + (size_t)(m0 + r0_) * K + k0_;
    const float* Ap1 = A + (size_t)(m0 + r1_) * K + k1_;
    const float* Wp0 = W + (size_t)(n0 + r0_) * K + k0_;
    const float* Wp1 = W + (size_t)(n0 + r1_) * K + k1_;

    ull acc[4][4];
    #pragma unroll
    for (int i = 0; i < 4; i++)
        #pragma unroll
        for (int j = 0; j < 4; j++) acc[i][j] = 0ull;

    {
        float4 a0 = *(const float4*)Ap0;
        float4 a1 = *(const float4*)Ap1;
        float4 b0 = *(const float4*)Wp0;
        float4 b1 = *(const float4*)Wp1;
        As[0][k0_ + 0][r0_] = a0.x; As[0][k0_ + 1][r0_] = a0.y; As[0][k0_ + 2][r0_] = a0.z; As[0][k0_ + 3][r0_] = a0.w;
        As[0][k1_ + 0][r1_] = a1.x; As[0][k1_ + 1][r1_] = a1.y; As[0][k1_ + 2][r1_] = a1.z; As[0][k1_ + 3][r1_] = a1.w;
        Bs[0][k0_ + 0][r0_] = b0.x; Bs[0][k0_ + 1][r0_] = b0.y; Bs[0][k0_ + 2][r0_] = b0.z; Bs[0][k0_ + 3][r0_] = b0.w;
        Bs[0][k1_ + 0][r1_] = b1.x; Bs[0][k1_ + 1][r1_] = b1.y; Bs[0][k1_ + 2][r1_] = b1.z; Bs[0][k1_ + 3][r1_] = b1.w;
    }
    __syncthreads();

    const int nk = K >> 4;
    for (int ko = 0; ko < nk; ko++) {
        int cur = ko & 1, nxt = cur ^ 1;
        float4 qa0, qa1, qb0, qb1;
        if (ko + 1 < nk) {
            qa0 = *(const float4*)(Ap0 + (ko + 1) * 16);
            qa1 = *(const float4*)(Ap1 + (ko + 1) * 16);
            qb0 = *(const float4*)(Wp0 + (ko + 1) * 16);
            qb1 = *(const float4*)(Wp1 + (ko + 1) * 16);
        }
        #pragma unroll
        for (int kk = 0; kk < 16; kk++) {
            ulonglong2 a01 = *(const ulonglong2*)&As[cur][kk][ty * 8];
            ulonglong2 a23 = *(const ulonglong2*)&As[cur][kk][ty * 8 + 4];
            float4 bf = *(const float4*)&Bs[cur][kk][tx * 4];
            ull aa[4] = {a01.x, a01.y, a23.x, a23.y};
            ull bb[4] = {dup2(bf.x), dup2(bf.y), dup2(bf.z), dup2(bf.w)};
            #pragma unroll
            for (int i = 0; i < 4; i++)
                #pragma unroll
                for (int j = 0; j < 4; j++) fma2(acc[i][j], aa[i], bb[j]);
        }
        if (ko + 1 < nk) {
            As[nxt][k0_ + 0][r0_] = qa0.x; As[nxt][k0_ + 1][r0_] = qa0.y; As[nxt][k0_ + 2][r0_] = qa0.z; As[nxt][k0_ + 3][r0_] = qa0.w;
            As[nxt][k1_ + 0][r1_] = qa1.x; As[nxt][k1_ + 1][r1_] = qa1.y; As[nxt][k1_ + 2][r1_] = qa1.z; As[nxt][k1_ + 3][r1_] = qa1.w;
            Bs[nxt][k0_ + 0][r0_] = qb0.x; Bs[nxt][k0_ + 1][r0_] = qb0.y; Bs[nxt][k0_ + 2][r0_] = qb0.z; Bs[nxt][k0_ + 3][r0_] = qb0.w;
            Bs[nxt][k1_ + 0][r1_] = qb1.x; Bs[nxt][k1_ + 1][r1_] = qb1.y; Bs[nxt][k1_ + 2][r1_] = qb1.z; Bs[nxt][k1_ + 3][r1_] = qb1.w;
        }
        __syncthreads();
    }

    float bv[4];
    #pragma unroll
    for (int j = 0; j < 4; j++) bv[j] = bias[n0 + tx * 4 + j];

    #pragma unroll
    for (int i = 0; i < 4; i++) {
        int lm = ty * 8 + 2 * i;
        float v0[4], v1[4];
        float s0 = 0.0f, s1 = 0.0f;
        #pragma unroll
        for (int j = 0; j < 4; j++) {
            float2 v = unp(acc[i][j]);
            float a0 = __fadd_rn(v.x, bv[j]);
            float a1 = __fadd_rn(v.y, bv[j]);
            if (RELU) { a0 = fmaxf(a0, 0.0f); a1 = fmaxf(a1, 0.0f); }
            v0[j] = a0; v1[j] = a1;
            if (ZZ) {
                s0 = __fadd_rn(s0, __fmul_rn(a0, a0));
                s1 = __fadd_rn(s1, __fmul_rn(a1, a1));
            }
        }
        size_t base0 = (size_t)(m0 + lm) * N + n0 + tx * 4;
        *(float4*)&C[base0]     = make_float4(v0[0], v0[1], v0[2], v0[3]);
        *(float4*)&C[base0 + N] = make_float4(v1[0], v1[1], v1[2], v1[3]);
        if (ZZ) {
            atomicAdd(&rs[lm], s0);
            atomicAdd(&rs[lm + 1], s1);
        }
    }
    if (ZZ) {
        __syncthreads();
        if (tid < 64) atomicAdd(&g_buf[OFF_ZZ + m0 + tid], rs[tid]);
    }
}

// ---------------- pin_gemm: virtual A = [h | (1+gamma)*sm + beta] ----------------
__device__ __forceinline__ float4 pin_loadA(int row, int k) {
    if (k < HH) return *(const float4*)&g_buf[OFF_H + (size_t)row * HH + k];
    int j = k - HH;
    float4 gm = *(const float4*)&g_buf[OFF_GB + (size_t)row * 1024 + j];
    float4 bt = *(const float4*)&g_buf[OFF_GB + (size_t)row * 1024 + CC + j];
    float4 sm = *(const float4*)&g_buf[OFF_SM + (size_t)row * CC + j];
    float4 r;
    r.x = __fadd_rn(__fmul_rn(__fadd_rn(1.0f, gm.x), sm.x), bt.x);
    r.y = __fadd_rn(__fmul_rn(__fadd_rn(1.0f, gm.y), sm.y), bt.y);
    r.z = __fadd_rn(__fmul_rn(__fadd_rn(1.0f, gm.z), sm.z), bt.z);
    r.w = __fadd_rn(__fmul_rn(__fadd_rn(1.0f, gm.w), sm.w), bt.w);
    return r;
}

__global__ __launch_bounds__(128) void pin_gemm(
    const float* __restrict__ W, const float* __restrict__ bias,
    float* __restrict__ C) {
    const int N = HH, K = 1024;
    __shared__ __align__(16) float As[2][16][68];
    __shared__ __align__(16) float Bs[2][16][68];

    int tid = threadIdx.x, tx = tid & 15, ty = tid >> 4;
    int m0 = blockIdx.y * 64, n0 = blockIdx.x * 64;

    int f0 = tid, f1 = tid + 128;
    int r0_ = f0 >> 2, k0_ = (f0 & 3) * 4;
    int r1_ = f1 >> 2, k1_ = (f1 & 3) * 4;
    const float* Wp0 = W + (size_t)(n0 + r0_) * K + k0_;
    const float* Wp1 = W + (size_t)(n0 + r1_) * K + k1_;

    ull acc[4][4];
    #pragma unroll
    for (int i = 0; i < 4; i++)
        #pragma unroll
        for (int j = 0; j < 4; j++) acc[i][j] = 0ull;

    {
        float4 a0 = pin_loadA(m0 + r0_, k0_);
        float4 a1 = pin_loadA(m0 + r1_, k1_);
        float4 b0 = *(const float4*)Wp0;
        float4 b1 = *(const float4*)Wp1;
        As[0][k0_ + 0][r0_] = a0.x; As[0][k0_ + 1][r0_] = a0.y; As[0][k0_ + 2][r0_] = a0.z; As[0][k0_ + 3][r0_] = a0.w;
        As[0][k1_ + 0][r1_] = a1.x; As[0][k1_ + 1][r1_] = a1.y; As[0][k1_ + 2][r1_] = a1.z; As[0][k1_ + 3][r1_] = a1.w;
        Bs[0][k0_ + 0][r0_] = b0.x; Bs[0][k0_ + 1][r0_] = b0.y; Bs[0][k0_ + 2][r0_] = b0.z; Bs[0][k0_ + 3][r0_] = b0.w;
        Bs[0][k1_ + 0][r1_] = b1.x; Bs[0][k1_ + 1][r1_] = b1.y; Bs[0][k1_ + 2][r1_] = b1.z; Bs[0][k1_ + 3][r1_] = b1.w;
    }
    __syncthreads();

    const int nk = K >> 4;
    for (int ko = 0; ko < nk; ko++) {
        int cur = ko & 1, nxt = cur ^ 1;
        float4 qa0, qa1, qb0, qb1;
        if (ko + 1 < nk) {
            qa0 = pin_loadA(m0 + r0_, (ko + 1) * 16 + k0_);
            qa1 = pin_loadA(m0 + r1_, (ko + 1) * 16 + k1_);
            qb0 = *(const float4*)(Wp0 + (ko + 1) * 16);
            qb1 = *(const float4*)(Wp1 + (ko + 1) * 16);
        }
        #pragma unroll
        for (int kk = 0; kk < 16; kk++) {
            ulonglong2 a01 = *(const ulonglong2*)&As[cur][kk][ty * 8];
            ulonglong2 a23 = *(const ulonglong2*)&As[cur][kk][ty * 8 + 4];
            float4 bf = *(const float4*)&Bs[cur][kk][tx * 4];
            ull aa[4] = {a01.x, a01.y, a23.x, a23.y};
            ull bb[4] = {dup2(bf.x), dup2(bf.y), dup2(bf.z), dup2(bf.w)};
            #pragma unroll
            for (int i = 0; i < 4; i++)
                #pragma unroll
                for (int j = 0; j < 4; j++) fma2(acc[i][j], aa[i], bb[j]);
        }
        if (ko + 1 < nk) {
            As[nxt][k0_ + 0][r0_] = qa0.x; As[nxt][k0_ + 1][r0_] = qa0.y; As[nxt][k0_ + 2][r0_] = qa0.z; As[nxt][k0_ + 3][r0_] = qa0.w;
            As[nxt][k1_ + 0][r1_] = qa1.x; As[nxt][k1_ + 1][r1_] = qa1.y; As[nxt][k1_ + 2][r1_] = qa1.z; As[nxt][k1_ + 3][r1_] = qa1.w;
            Bs[nxt][k0_ + 0][r0_] = qb0.x; Bs[nxt][k0_ + 1][r0_] = qb0.y; Bs[nxt][k0_ + 2][r0_] = qb0.z; Bs[nxt][k0_ + 3][r0_] = qb0.w;
            Bs[nxt][k1_ + 0][r1_] = qb1.x; Bs[nxt][k1_ + 1][r1_] = qb1.y; Bs[nxt][k1_ + 2][r1_] = qb1.z; Bs[nxt][k1_ + 3][r1_] = qb1.w;
        }
        __syncthreads();
    }

    float bv[4];
    #pragma unroll
    for (int j = 0; j < 4; j++) bv[j] = bias[n0 + tx * 4 + j];

    #pragma unroll
    for (int i = 0; i < 4; i++) {
        int lm = ty * 8 + 2 * i;
        float v0[4], v1[4];
        #pragma unroll
        for (int j = 0; j < 4; j++) {
            float2 v = unp(acc[i][j]);
            v0[j] = fmaxf(__fadd_rn(v.x, bv[j]), 0.0f);
            v1[j] = fmaxf(__fadd_rn(v.y, bv[j]), 0.0f);
        }
        size_t base0 = (size_t)(m0 + lm) * N + n0 + tx * 4;
        *(float4*)&C[base0]     = make_float4(v0[0], v0[1], v0[2], v0[3]);
        *(float4*)&C[base0 + N] = make_float4(v1[0], v1[1], v1[2], v1[3]);
    }
}

// ---------------- GRU fuse (float4) ----------------
__global__ void gru_fuse() {
    int i = blockIdx.x * blockDim.x + threadIdx.x;
    if (i >= BB * HH / 4) return;
    int b = i >> 7, j = (i & 127) * 4;
    const float* gx = g_buf + OFF_GX + (size_t)b * G3;
    const float* gh = g_buf + OFF_GH + (size_t)b * G3;
    float4 xr = *(const float4*)&gx[j];
    float4 xz = *(const float4*)&gx[HH + j];
    float4 xn = *(const float4*)&gx[2 * HH + j];
    float4 hr = *(const float4*)&gh[j];
    float4 hz = *(const float4*)&gh[HH + j];
    float4 hn = *(const float4*)&gh[2 * HH + j];
    float4 hv = *(const float4*)&g_buf[OFF_H + b * HH + j];
    float4 o;
    {
        float r = sigf(__fadd_rn(xr.x, hr.x));
        float zg = sigf(__fadd_rn(xz.x, hz.x));
        float n = tanhf(__fadd_rn(xn.x, __fmul_rn(r, hn.x)));
        o.x = __fadd_rn(__fmul_rn(__fsub_rn(1.0f, zg), n), __fmul_rn(zg, hv.x));
    }
    {
        float r = sigf(__fadd_rn(xr.y, hr.y));
        float zg = sigf(__fadd_rn(xz.y, hz.y));
        float n = tanhf(__fadd_rn(xn.y, __fmul_rn(r, hn.y)));
        o.y = __fadd_rn(__fmul_rn(__fsub_rn(1.0f, zg), n), __fmul_rn(zg, hv.y));
    }
    {
        float r = sigf(__fadd_rn(xr.z, hr.z));
        float zg = sigf(__fadd_rn(xz.z, hz.z));
        float n = tanhf(__fadd_rn(xn.z, __fmul_rn(r, hn.z)));
        o.z = __fadd_rn(__fmul_rn(__fsub_rn(1.0f, zg), n), __fmul_rn(zg, hv.z));
    }
    {
        float r = sigf(__fadd_rn(xr.w, hr.w));
        float zg = sigf(__fadd_rn(xz.w, hz.w));
        float n = tanhf(__fadd_rn(xn.w, __fmul_rn(r, hn.w)));
        o.w = __fadd_rn(__fmul_rn(__fsub_rn(1.0f, zg), n), __fmul_rn(zg, hv.w));
    }
    *(float4*)&g_buf[OFF_H + b * HH + j] = o;
}

// ---------------- post-VQ (also resets dmin/zz for next step) ----------------
__global__ void postvq(float* __restrict__ out, int t) {
    int b = blockIdx.x, d = threadIdx.x;
    unsigned idx = (unsigned)(((ull*)(g_buf + OFF_DMIN))[b] & 0xFFFFFFFFULL);
    float zv = g_buf[OFF_Z + b * DD + d];
    float zq = g_buf[OFF_CB + (size_t)idx * DD + d];
    float ste = __fadd_rn(zv, __fsub_rn(zq, zv));
    out[OUT_CODES + ((size_t)b * TT + t) * DD + d] = ste;
    out[OUT_ZC + ((size_t)b * TT + t) * DD + d] = zv;
    g_buf[OFF_PREV + b * DD + d] = ste;
    if (d == 0) {
        out[OUT_IDX + b * TT + t] = (float)idx;
        atomicAdd(&g_buf[OFF_COUNTS + idx], 1.0f);
    }
    atomicAdd(&g_buf[OFF_DW + (size_t)idx * DD + d], zv);
    float diff = __fsub_rn(zv, zq);
    __shared__ float sred[256];
    sred[d] = __fmul_rn(diff, diff);
    __syncthreads();
    #pragma unroll
    for (int o = 128; o; o >>= 1) {
        if (d < o) sred[d] = __fadd_rn(sred[d], sred[d + o]);
        __syncthreads();
    }
    if (d == 0) {
        atomicAdd(&g_buf[OFF_LOSS], sred[0]);
        ((ull*)(g_buf + OFF_DMIN))[b] = 0xFFFFFFFFFFFFFFFFULL;
        g_buf[OFF_ZZ + b] = 0.0f;
    }
}

// ---------------- EMA update (analytic n_tot) ----------------
__global__ void ema_c(float nt) {
    int k = blockIdx.x, d = threadIdx.x;
    float csv = __fadd_rn(__fmul_rn(0.99f, g_buf[OFF_CS + k]),
                          __fmul_rn(0.01f, g_buf[OFF_COUNTS + k]));
    float s = __fmul_rn(__fdiv_rn(__fadd_rn(csv, 1e-5f),
                                  __fadd_rn(nt, 0.08192f)), nt);
    int i = k * DD + d;
    float e = __fadd_rn(__fmul_rn(0.99f, g_buf[OFF_EW + i]),
                        __fmul_rn(0.01f, g_buf[OFF_DW + i]));
    g_buf[OFF_EW + i] = e;
    float cbv = __fdiv_rn(e, s);
    g_buf[OFF_CB + i] = cbv;
    g_buf[OFF_DW + i] = 0.0f;
    __shared__ float sr[256];
    sr[d] = __fmul_rn(cbv, cbv);
    __syncthreads();
    #pragma unroll
    for (int o = 128; o; o >>= 1) {
        if (d < o) sr[d] = __fadd_rn(sr[d], sr[d + o]);
        __syncthreads();
    }
    if (d == 0) {
        g_buf[OFF_CBSQ + k] = sr[0];
        g_buf[OFF_CS + k] = s;
        g_buf[OFF_COUNTS + k] = 0.0f;
    }
}

// ---------------- finalize ----------------
__global__ void write_h(float* __restrict__ out) {
    int i = blockIdx.x * blockDim.x + threadIdx.x;
    if (i < BB * HH) out[OUT_H + i] = g_buf[OFF_H + i];
    if (i == 0)
        out[OUT_LOSS] = 0.25f * (g_buf[OFF_LOSS] / 262144.0f) * 0.125f;
}

// ---------------- launch ----------------
extern "C" void kernel_launch(void* const* d_in, const int* in_sizes, int n_in,
                              void* d_out, int out_size) {
    const float* sf   = (const float*)d_in[0];
    const float* bos  = (const float*)d_in[1];
    const float* W_ih = (const float*)d_in[2];
    const float* W_hh = (const float*)d_in[3];
    const float* b_ih = (const float*)d_in[4];
    const float* b_hh = (const float*)d_in[5];
    const float* Wg   = (const float*)d_in[6];
    const float* bg   = (const float*)d_in[7];
    const float* Wb   = (const float*)d_in[8];
    const float* bb   = (const float*)d_in[9];
    const float* W1   = (const float*)d_in[10];
    const float* b1   = (const float*)d_in[11];
    const float* W2   = (const float*)d_in[12];
    const float* b2   = (const float*)d_in[13];
    const float* cb_in = (const float*)d_in[14];
    const float* cs_in = (const float*)d_in[15];
    const float* ew_in = (const float*)d_in[16];
    float* out = (float*)d_out;

    void* sym = nullptr;
    cudaGetSymbolAddress(&sym, g_buf);
    float* g = (float*)sym;

    float ntf[TT];
    {
        double S = 0.0;
        double dec = (double)0.99f;
        double add = 1024.0 * (double)0.01f;
        for (int t = 0; t < TT; t++) { S = dec * S + add; ntf[t] = (float)S; }
    }

    init_copy<<<(KK * DD + 255) / 256, 256>>>(cb_in, cs_in, ew_in);
    init_state<<<(BB * HH + 255) / 256, 256>>>(bos);
    packw<<<(CC * HH + 255) / 256, 256>>>(Wg, bg, Wb, bb);
    smean_kernel<<<(BB * CC / 4 * 32 + 255) / 256, 256>>>(sf);
    cbsq_init<<<KK, 256>>>();

    for (int t = 0; t < TT; t++) {
        gru_gemm<<<dim3(G3 / 128, BB / 128, 2), 256>>>(W_ih, b_ih, W_hh, b_hh);
        gru_fuse<<<(BB * HH / 4 + 255) / 256, 256>>>();
        med_gemm<0, 0><<<dim3(1024 / 64, BB / 64), 128>>>(g + OFF_H, g + OFF_WGB, g + OFF_BGB, g + OFF_GB, 1024, HH);
        pin_gemm<<<dim3(HH / 64, BB / 64), 128>>>(W1, b1, g + OFF_Z1);
        med_gemm<0, 1><<<dim3(DD / 64, BB / 64), 128>>>(g + OFF_Z1, W2, b2, g + OFF_Z, DD, HH);
        vq_gemm<<<dim3(KK / 128, BB / 128), 256>>>();
        postvq<<<BB, 256>>>(out, t);
        ema_c<<<KK, 256>>>(ntf[t]);
    }

    write_h<<<(BB * HH + 255) / 256, 256>>>(out);
    (void)in_sizes; (void)n_in; (void)out_size;
}

// round 17
// speedup vs baseline: 1.1608x; 1.1608x over previous
#include <cuda_runtime.h>
#include <cuda_bf16.h>
#include <math.h>
#include <stdint.h>

// Problem constants
#define BB 1024
#define CC 512
#define DD 256
#define KK 8192
#define HH 512
#define G3 1536
#define TT 8
#define HW 49

// ---------------- scratch layout ----------------
#define OFF_PREV    0
#define OFF_H       262144
#define OFF_GX      786432
#define OFF_GH      2359296
#define OFF_WGB     4980736
#define OFF_BGB     5505024
#define OFF_Z1      6029312
#define OFF_Z       6553600
#define OFF_SM      6815744
#define OFF_CB      7340032
#define OFF_EW      9437184
#define OFF_DW      11534336
#define OFF_CS      13631488
#define OFF_COUNTS  13647872
#define OFF_CBSQ    13656064
#define OFF_ZZ      13664256
#define OFF_LOSS    13665313
#define OFF_DMIN    13665316
#define G_TOTAL     13667368

#define OFF_GB OFF_GX

__device__ float g_buf[G_TOTAL];

// output layout
#define OUT_H     0
#define OUT_CODES 524288
#define OUT_IDX   2621440
#define OUT_ZC    2629632
#define OUT_LOSS  4726784

typedef unsigned long long ull;

// ---------------- helpers ----------------
__device__ __forceinline__ float sigf(float x) { return 1.0f / (1.0f + expf(-x)); }

__device__ __forceinline__ unsigned fenc(float f) {
    unsigned u = __float_as_uint(f);
    return (u & 0x80000000u) ? ~u : (u | 0x80000000u);
}

__device__ __forceinline__ ull dup2(float x) {
    ull r; asm("mov.b64 %0,{%1,%1};" : "=l"(r) : "f"(x)); return r;
}
__device__ __forceinline__ void fma2(ull& acc, ull a, ull b) {
    asm("fma.rn.f32x2 %0,%1,%2,%0;" : "+l"(acc) : "l"(a), "l"(b));
}
__device__ __forceinline__ float2 unp(ull v) {
    float2 f; asm("mov.b64 {%0,%1},%2;" : "=f"(f.x), "=f"(f.y) : "l"(v)); return f;
}

// ---------------- init ----------------
__global__ void init_copy(const float* __restrict__ cb_in,
                          const float* __restrict__ cs_in,
                          const float* __restrict__ ew_in) {
    int i = blockIdx.x * blockDim.x + threadIdx.x;
    if (i < KK * DD) {
        g_buf[OFF_CB + i] = cb_in[i];
        g_buf[OFF_EW + i] = ew_in[i];
    }
    if (i < KK) g_buf[OFF_CS + i] = cs_in[i];
}

__global__ void init_state(const float* __restrict__ bos) {
    int i = blockIdx.x * blockDim.x + threadIdx.x;
    if (i < BB * DD) g_buf[OFF_PREV + i] = bos[i & (DD - 1)];
    if (i < BB * HH) g_buf[OFF_H + i] = 0.0f;
    if (i < BB) {
        ((ull*)(g_buf + OFF_DMIN))[i] = 0xFFFFFFFFFFFFFFFFULL;
        g_buf[OFF_ZZ + i] = 0.0f;
    }
    if (i == 0) g_buf[OFF_LOSS] = 0.0f;
}

__global__ void packw(const float* __restrict__ Wg, const float* __restrict__ bg,
                      const float* __restrict__ Wb, const float* __restrict__ bbp) {
    int i = blockIdx.x * blockDim.x + threadIdx.x;
    if (i < CC * HH) {
        g_buf[OFF_WGB + i] = Wg[i];
        g_buf[OFF_WGB + CC * HH + i] = Wb[i];
    }
    if (i < CC) {
        g_buf[OFF_BGB + i] = bg[i];
        g_buf[OFF_BGB + CC + i] = bbp[i];
    }
}

__global__ void cbsq_init() {
    int k = blockIdx.x, d = threadIdx.x;
    float v = g_buf[OFF_CB + k * DD + d];
    __shared__ float s[256];
    s[d] = __fmul_rn(v, v);
    __syncthreads();
    #pragma unroll
    for (int o = 128; o; o >>= 1) {
        if (d < o) s[d] = __fadd_rn(s[d], s[d + o]);
        __syncthreads();
    }
    if (d == 0) g_buf[OFF_CBSQ + k] = s[0];
}

// ---------------- spatial mean: warp per 4 channels ----------------
__global__ void smean_kernel(const float* __restrict__ sf) {
    int w = (blockIdx.x * blockDim.x + threadIdx.x) >> 5;
    int lane = threadIdx.x & 31;
    if (w >= BB * CC / 4) return;
    const float* p = sf + (size_t)w * 4 * HW;
    float s[4];
    #pragma unroll
    for (int c = 0; c < 4; c++) {
        s[c] = p[c * HW + lane];
        if (lane + 32 < HW) s[c] = __fadd_rn(s[c], p[c * HW + lane + 32]);
    }
    #pragma unroll
    for (int c = 0; c < 4; c++) {
        #pragma unroll
        for (int o = 16; o; o >>= 1) s[c] = __fadd_rn(s[c], __shfl_down_sync(0xffffffffu, s[c], o));
        if (lane == 0) g_buf[OFF_SM + w * 4 + c] = s[c] / 49.0f;
    }
}

// =====================================================================
#define BIGP (128 + 4)

// ---------------- GRU dual GEMM: tile 128x64, BK=16, 256 threads, 8Mx4N/thread ----------------
// grid (G3/64, BB/128, 2) = 384 CTAs -> max 3 CTAs/SM -> balanced wave
__global__ __launch_bounds__(256, 2) void gru_gemm(
    const float* __restrict__ W_ih, const float* __restrict__ b_ih,
    const float* __restrict__ W_hh, const float* __restrict__ b_hh) {
    __shared__ __align__(16) float As[2][16][BIGP];
    __shared__ __align__(16) float Bs[2][16][68];
    const float* A; const float* W; const float* bias; float* out; int K;
    if (blockIdx.z == 0) { A = g_buf + OFF_PREV; W = W_ih; bias = b_ih; out = g_buf + OFF_GX; K = DD; }
    else                 { A = g_buf + OFF_H;    W = W_hh; bias = b_hh; out = g_buf + OFF_GH; K = HH; }

    int tid = threadIdx.x, tx = tid & 15, ty = tid >> 4;
    int m0 = blockIdx.y * 128, n0 = blockIdx.x * 64;
    // A loader: 512 float4 tasks (2/thread); B: 256 tasks (1/thread)
    int ar = tid >> 2, ak = (tid & 3) * 4;
    const float* Ap0 = A + (size_t)(m0 + ar) * K + ak;
    const float* Ap1 = Ap0 + (size_t)64 * K;
    const float* Bp  = W + (size_t)(n0 + ar) * K + ak;

    ull acc[4][4];
    #pragma unroll
    for (int i = 0; i < 4; i++)
        #pragma unroll
        for (int j = 0; j < 4; j++) acc[i][j] = 0ull;

    {
        float4 a0 = *(const float4*)Ap0;
        float4 a1 = *(const float4*)Ap1;
        float4 b0 = *(const float4*)Bp;
        As[0][ak + 0][ar] = a0.x; As[0][ak + 1][ar] = a0.y; As[0][ak + 2][ar] = a0.z; As[0][ak + 3][ar] = a0.w;
        As[0][ak + 0][ar + 64] = a1.x; As[0][ak + 1][ar + 64] = a1.y; As[0][ak + 2][ar + 64] = a1.z; As[0][ak + 3][ar + 64] = a1.w;
        Bs[0][ak + 0][ar] = b0.x; Bs[0][ak + 1][ar] = b0.y; Bs[0][ak + 2][ar] = b0.z; Bs[0][ak + 3][ar] = b0.w;
    }
    __syncthreads();

    int nk = K >> 4;
    for (int ko = 0; ko < nk; ko++) {
        int cur = ko & 1, nxt = cur ^ 1;
        float4 qa0, qa1, qb0;
        if (ko + 1 < nk) {
            qa0 = *(const float4*)(Ap0 + (ko + 1) * 16);
            qa1 = *(const float4*)(Ap1 + (ko + 1) * 16);
            qb0 = *(const float4*)(Bp + (ko + 1) * 16);
        }
        #pragma unroll
        for (int kk = 0; kk < 16; kk++) {
            ulonglong2 a01 = *(const ulonglong2*)&As[cur][kk][ty * 8];
            ulonglong2 a23 = *(const ulonglong2*)&As[cur][kk][ty * 8 + 4];
            float4 bf = *(const float4*)&Bs[cur][kk][tx * 4];
            ull aa[4] = {a01.x, a01.y, a23.x, a23.y};
            ull bb[4] = {dup2(bf.x), dup2(bf.y), dup2(bf.z), dup2(bf.w)};
            #pragma unroll
            for (int i = 0; i < 4; i++)
                #pragma unroll
                for (int j = 0; j < 4; j++) fma2(acc[i][j], aa[i], bb[j]);
        }
        if (ko + 1 < nk) {
            As[nxt][ak + 0][ar] = qa0.x; As[nxt][ak + 1][ar] = qa0.y; As[nxt][ak + 2][ar] = qa0.z; As[nxt][ak + 3][ar] = qa0.w;
            As[nxt][ak + 0][ar + 64] = qa1.x; As[nxt][ak + 1][ar + 64] = qa1.y; As[nxt][ak + 2][ar + 64] = qa1.z; As[nxt][ak + 3][ar + 64] = qa1.w;
            Bs[nxt][ak + 0][ar] = qb0.x; Bs[nxt][ak + 1][ar] = qb0.y; Bs[nxt][ak + 2][ar] = qb0.z; Bs[nxt][ak + 3][ar] = qb0.w;
        }
        __syncthreads();
    }

    float bv[4];
    #pragma unroll
    for (int j = 0; j < 4; j++) bv[j] = bias[n0 + tx * 4 + j];
    #pragma unroll
    for (int i = 0; i < 4; i++) {
        float r0[4], r1[4];
        #pragma unroll
        for (int j = 0; j < 4; j++) {
            float2 v = unp(acc[i][j]);
            r0[j] = __fadd_rn(v.x, bv[j]);
            r1[j] = __fadd_rn(v.y, bv[j]);
        }
        size_t base0 = (size_t)(m0 + ty * 8 + 2 * i) * G3 + n0 + tx * 4;
        *(float4*)&out[base0]      = make_float4(r0[0], r0[1], r0[2], r0[3]);
        *(float4*)&out[base0 + G3] = make_float4(r1[0], r1[1], r1[2], r1[3]);
    }
}

// ---------------- VQ GEMM: tile 128x64, BK=16 + fused distance/argmin ----------------
// grid (KK/64, BB/128) = 1024 CTAs -> max 7/SM -> near-ideal balance
__global__ __launch_bounds__(256, 2) void vq_gemm() {
    __shared__ __align__(16) float As[2][16][BIGP];
    __shared__ __align__(16) float Bs[2][16][68];
    const float* A = g_buf + OFF_Z;
    const float* W = g_buf + OFF_CB;
    const int K = DD;

    int tid = threadIdx.x, tx = tid & 15, ty = tid >> 4;
    int m0 = blockIdx.y * 128, n0 = blockIdx.x * 64;
    int ar = tid >> 2, ak = (tid & 3) * 4;
    const float* Ap0 = A + (size_t)(m0 + ar) * K + ak;
    const float* Ap1 = Ap0 + (size_t)64 * K;
    const float* Bp  = W + (size_t)(n0 + ar) * K + ak;

    ull acc[4][4];
    #pragma unroll
    for (int i = 0; i < 4; i++)
        #pragma unroll
        for (int j = 0; j < 4; j++) acc[i][j] = 0ull;

    {
        float4 a0 = *(const float4*)Ap0;
        float4 a1 = *(const float4*)Ap1;
        float4 b0 = *(const float4*)Bp;
        As[0][ak + 0][ar] = a0.x; As[0][ak + 1][ar] = a0.y; As[0][ak + 2][ar] = a0.z; As[0][ak + 3][ar] = a0.w;
        As[0][ak + 0][ar + 64] = a1.x; As[0][ak + 1][ar + 64] = a1.y; As[0][ak + 2][ar + 64] = a1.z; As[0][ak + 3][ar + 64] = a1.w;
        Bs[0][ak + 0][ar] = b0.x; Bs[0][ak + 1][ar] = b0.y; Bs[0][ak + 2][ar] = b0.z; Bs[0][ak + 3][ar] = b0.w;
    }
    __syncthreads();

    const int nk = K >> 4;
    for (int ko = 0; ko < nk; ko++) {
        int cur = ko & 1, nxt = cur ^ 1;
        float4 qa0, qa1, qb0;
        if (ko + 1 < nk) {
            qa0 = *(const float4*)(Ap0 + (ko + 1) * 16);
            qa1 = *(const float4*)(Ap1 + (ko + 1) * 16);
            qb0 = *(const float4*)(Bp + (ko + 1) * 16);
        }
        #pragma unroll
        for (int kk = 0; kk < 16; kk++) {
            ulonglong2 a01 = *(const ulonglong2*)&As[cur][kk][ty * 8];
            ulonglong2 a23 = *(const ulonglong2*)&As[cur][kk][ty * 8 + 4];
            float4 bf = *(const float4*)&Bs[cur][kk][tx * 4];
            ull aa[4] = {a01.x, a01.y, a23.x, a23.y};
            ull bb[4] = {dup2(bf.x), dup2(bf.y), dup2(bf.z), dup2(bf.w)};
            #pragma unroll
            for (int i = 0; i < 4; i++)
                #pragma unroll
                for (int j = 0; j < 4; j++) fma2(acc[i][j], aa[i], bb[j]);
        }
        if (ko + 1 < nk) {
            As[nxt][ak + 0][ar] = qa0.x; As[nxt][ak + 1][ar] = qa0.y; As[nxt][ak + 2][ar] = qa0.z; As[nxt][ak + 3][ar] = qa0.w;
            As[nxt][ak + 0][ar + 64] = qa1.x; As[nxt][ak + 1][ar + 64] = qa1.y; As[nxt][ak + 2][ar + 64] = qa1.z; As[nxt][ak + 3][ar + 64] = qa1.w;
            Bs[nxt][ak + 0][ar] = qb0.x; Bs[nxt][ak + 1][ar] = qb0.y; Bs[nxt][ak + 2][ar] = qb0.z; Bs[nxt][ak + 3][ar] = qb0.w;
        }
        __syncthreads();
    }

    float cq[4];
    #pragma unroll
    for (int j = 0; j < 4; j++) cq[j] = g_buf[OFF_CBSQ + n0 + tx * 4 + j];

    #pragma unroll
    for (int i = 0; i < 4; i++) {
        int m = m0 + ty * 8 + 2 * i;
        float zz0 = g_buf[OFF_ZZ + m];
        float zz1 = g_buf[OFF_ZZ + m + 1];
        ull b0 = 0xFFFFFFFFFFFFFFFFULL, b1 = 0xFFFFFFFFFFFFFFFFULL;
        #pragma unroll
        for (int j = 0; j < 4; j++) {
            unsigned n = (unsigned)(n0 + tx * 4 + j);
            float2 v = unp(acc[i][j]);
            float d0 = __fadd_rn(__fsub_rn(zz0, __fmul_rn(2.0f, v.x)), cq[j]);
            float d1 = __fadd_rn(__fsub_rn(zz1, __fmul_rn(2.0f, v.y)), cq[j]);
            ull k0 = ((ull)fenc(d0) << 32) | n;
            ull k1 = ((ull)fenc(d1) << 32) | n;
            b0 = min(b0, k0);
            b1 = min(b1, k1);
        }
        #pragma unroll
        for (int o = 1; o < 16; o <<= 1) {
            b0 = min(b0, __shfl_xor_sync(0xffffffffu, b0, o));
            b1 = min(b1, __shfl_xor_sync(0xffffffffu, b1, o));
        }
        if (tx == 0) {
            atomicMin((ull*)(g_buf + OFF_DMIN) + m,     b0);
            atomicMin((ull*)(g_buf + OFF_DMIN) + m + 1, b1);
        }
    }
}

// ---------------- MED GEMM: 64x64, BK=16, 128 threads ----------------
template <int RELU, int ZZ>
__global__ __launch_bounds__(128) void med_gemm(
    const float* __restrict__ A, const float* __restrict__ W,
    const float* __restrict__ bias, float* __restrict__ C,
    int N, int K) {
    __shared__ __align__(16) float As[2][16][68];
    __shared__ __align__(16) float Bs[2][16][68];
    __shared__ float rs[64];

    int tid = threadIdx.x, tx = tid & 15, ty = tid >> 4;
    int m0 = blockIdx.y * 64, n0 = blockIdx.x * 64;
    if (ZZ && tid < 64) rs[tid] = 0.0f;

    int f0 = tid, f1 = tid + 128;
    int r0_ = f0 >> 2, k0_ = (f0 & 3) * 4;
    int r1_ = f1 >> 2, k1_ = (f1 & 3) * 4;
    const float* Ap0 = A + (size_t)(m0 + r0_) * K + k0_;
    const float* Ap1 = A + (size_t)(m0 + r1_) * K + k1_;
    const float* Wp0 = W + (size_t)(n0 + r0_) * K + k0_;
    const float* Wp1 = W + (size_t)(n0 + r1_) * K + k1_;

    ull acc[4][4];
    #pragma unroll
    for (int i = 0; i < 4; i++)
        #pragma unroll
        for (int j = 0; j < 4; j++) acc[i][j] = 0ull;

    {
        float4 a0 = *(const float4*)Ap0;
        float4 a1 = *(const float4*)Ap1;
        float4 b0 = *(const float4*)Wp0;
        float4 b1 = *(const float4*)Wp1;
        As[0][k0_ + 0][r0_] = a0.x; As[0][k0_ + 1][r0_] = a0.y; As[0][k0_ + 2][r0_] = a0.z; As[0][k0_ + 3][r0_] = a0.w;
        As[0][k1_ + 0][r1_] = a1.x; As[0][k1_ + 1][r1_] = a1.y; As[0][k1_ + 2][r1_] = a1.z; As[0][k1_ + 3][r1_] = a1.w;
        Bs[0][k0_ + 0][r0_] = b0.x; Bs[0][k0_ + 1][r0_] = b0.y; Bs[0][k0_ + 2][r0_] = b0.z; Bs[0][k0_ + 3][r0_] = b0.w;
        Bs[0][k1_ + 0][r1_] = b1.x; Bs[0][k1_ + 1][r1_] = b1.y; Bs[0][k1_ + 2][r1_] = b1.z; Bs[0][k1_ + 3][r1_] = b1.w;
    }
    __syncthreads();

    const int nk = K >> 4;
    for (int ko = 0; ko < nk; ko++) {
        int cur = ko & 1, nxt = cur ^ 1;
        float4 qa0, qa1, qb0, qb1;
        if (ko + 1 < nk) {
            qa0 = *(const float4*)(Ap0 + (ko + 1) * 16);
            qa1 = *(const float4*)(Ap1 + (ko + 1) * 16);
            qb0 = *(const float4*)(Wp0 + (ko + 1) * 16);
            qb1 = *(const float4*)(Wp1 + (ko + 1) * 16);
        }
        #pragma unroll
        for (int kk = 0; kk < 16; kk++) {
            ulonglong2 a01 = *(const ulonglong2*)&As[cur][kk][ty * 8];
            ulonglong2 a23 = *(const ulonglong2*)&As[cur][kk][ty * 8 + 4];
            float4 bf = *(const float4*)&Bs[cur][kk][tx * 4];
            ull aa[4] = {a01.x, a01.y, a23.x, a23.y};
            ull bb[4] = {dup2(bf.x), dup2(bf.y), dup2(bf.z), dup2(bf.w)};
            #pragma unroll
            for (int i = 0; i < 4; i++)
                #pragma unroll
                for (int j = 0; j < 4; j++) fma2(acc[i][j], aa[i], bb[j]);
        }
        if (ko + 1 < nk) {
            As[nxt][k0_ + 0][r0_] = qa0.x; As[nxt][k0_ + 1][r0_] = qa0.y; As[nxt][k0_ + 2][r0_] = qa0.z; As[nxt][k0_ + 3][r0_] = qa0.w;
            As[nxt][k1_ + 0][r1_] = qa1.x; As[nxt][k1_ + 1][r1_] = qa1.y; As[nxt][k1_ + 2][r1_] = qa1.z; As[nxt][k1_ + 3][r1_] = qa1.w;
            Bs[nxt][k0_ + 0][r0_] = qb0.x; Bs[nxt][k0_ + 1][r0_] = qb0.y; Bs[nxt][k0_ + 2][r0_] = qb0.z; Bs[nxt][k0_ + 3][r0_] = qb0.w;
            Bs[nxt][k1_ + 0][r1_] = qb1.x; Bs[nxt][k1_ + 1][r1_] = qb1.y; Bs[nxt][k1_ + 2][r1_] = qb1.z; Bs[nxt][k1_ + 3][r1_] = qb1.w;
        }
        __syncthreads();
    }

    float bv[4];
    #pragma unroll
    for (int j = 0; j < 4; j++) bv[j] = bias[n0 + tx * 4 + j];

    #pragma unroll
    for (int i = 0; i < 4; i++) {
        int lm = ty * 8 + 2 * i;
        float v0[4], v1[4];
        float s0 = 0.0f, s1 = 0.0f;
        #pragma unroll
        for (int j = 0; j < 4; j++) {
            float2 v = unp(acc[i][j]);
            float a0 = __fadd_rn(v.x, bv[j]);
            float a1 = __fadd_rn(v.y, bv[j]);
            if (RELU) { a0 = fmaxf(a0, 0.0f); a1 = fmaxf(a1, 0.0f); }
            v0[j] = a0; v1[j] = a1;
            if (ZZ) {
                s0 = __fadd_rn(s0, __fmul_rn(a0, a0));
                s1 = __fadd_rn(s1, __fmul_rn(a1, a1));
            }
        }
        size_t base0 = (size_t)(m0 + lm) * N + n0 + tx * 4;
        *(float4*)&C[base0]     = make_float4(v0[0], v0[1], v0[2], v0[3]);
        *(float4*)&C[base0 + N] = make_float4(v1[0], v1[1], v1[2], v1[3]);
        if (ZZ) {
            atomicAdd(&rs[lm], s0);
            atomicAdd(&rs[lm + 1], s1);
        }
    }
    if (ZZ) {
        __syncthreads();
        if (tid < 64) atomicAdd(&g_buf[OFF_ZZ + m0 + tid], rs[tid]);
    }
}

// ---------------- pin_gemm: virtual A = [h | (1+gamma)*sm + beta] ----------------
__device__ __forceinline__ float4 pin_loadA(int row, int k) {
    if (k < HH) return *(const float4*)&g_buf[OFF_H + (size_t)row * HH + k];
    int j = k - HH;
    float4 gm = *(const float4*)&g_buf[OFF_GB + (size_t)row * 1024 + j];
    float4 bt = *(const float4*)&g_buf[OFF_GB + (size_t)row * 1024 + CC + j];
    float4 sm = *(const float4*)&g_buf[OFF_SM + (size_t)row * CC + j];
    float4 r;
    r.x = __fadd_rn(__fmul_rn(__fadd_rn(1.0f, gm.x), sm.x), bt.x);
    r.y = __fadd_rn(__fmul_rn(__fadd_rn(1.0f, gm.y), sm.y), bt.y);
    r.z = __fadd_rn(__fmul_rn(__fadd_rn(1.0f, gm.z), sm.z), bt.z);
    r.w = __fadd_rn(__fmul_rn(__fadd_rn(1.0f, gm.w), sm.w), bt.w);
    return r;
}

__global__ __launch_bounds__(128) void pin_gemm(
    const float* __restrict__ W, const float* __restrict__ bias,
    float* __restrict__ C) {
    const int N = HH, K = 1024;
    __shared__ __align__(16) float As[2][16][68];
    __shared__ __align__(16) float Bs[2][16][68];

    int tid = threadIdx.x, tx = tid & 15, ty = tid >> 4;
    int m0 = blockIdx.y * 64, n0 = blockIdx.x * 64;

    int f0 = tid, f1 = tid + 128;
    int r0_ = f0 >> 2, k0_ = (f0 & 3) * 4;
    int r1_ = f1 >> 2, k1_ = (f1 & 3) * 4;
    const float* Wp0 = W + (size_t)(n0 + r0_) * K + k0_;
    const float* Wp1 = W + (size_t)(n0 + r1_) * K + k1_;

    ull acc[4][4];
    #pragma unroll
    for (int i = 0; i < 4; i++)
        #pragma unroll
        for (int j = 0; j < 4; j++) acc[i][j] = 0ull;

    {
        float4 a0 = pin_loadA(m0 + r0_, k0_);
        float4 a1 = pin_loadA(m0 + r1_, k1_);
        float4 b0 = *(const float4*)Wp0;
        float4 b1 = *(const float4*)Wp1;
        As[0][k0_ + 0][r0_] = a0.x; As[0][k0_ + 1][r0_] = a0.y; As[0][k0_ + 2][r0_] = a0.z; As[0][k0_ + 3][r0_] = a0.w;
        As[0][k1_ + 0][r1_] = a1.x; As[0][k1_ + 1][r1_] = a1.y; As[0][k1_ + 2][r1_] = a1.z; As[0][k1_ + 3][r1_] = a1.w;
        Bs[0][k0_ + 0][r0_] = b0.x; Bs[0][k0_ + 1][r0_] = b0.y; Bs[0][k0_ + 2][r0_] = b0.z; Bs[0][k0_ + 3][r0_] = b0.w;
        Bs[0][k1_ + 0][r1_] = b1.x; Bs[0][k1_ + 1][r1_] = b1.y; Bs[0][k1_ + 2][r1_] = b1.z; Bs[0][k1_ + 3][r1_] = b1.w;
    }
    __syncthreads();

    const int nk = K >> 4;
    for (int ko = 0; ko < nk; ko++) {
        int cur = ko & 1, nxt = cur ^ 1;
        float4 qa0, qa1, qb0, qb1;
        if (ko + 1 < nk) {
            qa0 = pin_loadA(m0 + r0_, (ko + 1) * 16 + k0_);
            qa1 = pin_loadA(m0 + r1_, (ko + 1) * 16 + k1_);
            qb0 = *(const float4*)(Wp0 + (ko + 1) * 16);
            qb1 = *(const float4*)(Wp1 + (ko + 1) * 16);
        }
        #pragma unroll
        for (int kk = 0; kk < 16; kk++) {
            ulonglong2 a01 = *(const ulonglong2*)&As[cur][kk][ty * 8];
            ulonglong2 a23 = *(const ulonglong2*)&As[cur][kk][ty * 8 + 4];
            float4 bf = *(const float4*)&Bs[cur][kk][tx * 4];
            ull aa[4] = {a01.x, a01.y, a23.x, a23.y};
            ull bb[4] = {dup2(bf.x), dup2(bf.y), dup2(bf.z), dup2(bf.w)};
            #pragma unroll
            for (int i = 0; i < 4; i++)
                #pragma unroll
                for (int j = 0; j < 4; j++) fma2(acc[i][j], aa[i], bb[j]);
        }
        if (ko + 1 < nk) {
            As[nxt][k0_ + 0][r0_] = qa0.x; As[nxt][k0_ + 1][r0_] = qa0.y; As[nxt][k0_ + 2][r0_] = qa0.z; As[nxt][k0_ + 3][r0_] = qa0.w;
            As[nxt][k1_ + 0][r1_] = qa1.x; As[nxt][k1_ + 1][r1_] = qa1.y; As[nxt][k1_ + 2][r1_] = qa1.z; As[nxt][k1_ + 3][r1_] = qa1.w;
            Bs[nxt][k0_ + 0][r0_] = qb0.x; Bs[nxt][k0_ + 1][r0_] = qb0.y; Bs[nxt][k0_ + 2][r0_] = qb0.z; Bs[nxt][k0_ + 3][r0_] = qb0.w;
            Bs[nxt][k1_ + 0][r1_] = qb1.x; Bs[nxt][k1_ + 1][r1_] = qb1.y; Bs[nxt][k1_ + 2][r1_] = qb1.z; Bs[nxt][k1_ + 3][r1_] = qb1.w;
        }
        __syncthreads();
    }

    float bv[4];
    #pragma unroll
    for (int j = 0; j < 4; j++) bv[j] = bias[n0 + tx * 4 + j];

    #pragma unroll
    for (int i = 0; i < 4; i++) {
        int lm = ty * 8 + 2 * i;
        float v0[4], v1[4];
        #pragma unroll
        for (int j = 0; j < 4; j++) {
            float2 v = unp(acc[i][j]);
            v0[j] = fmaxf(__fadd_rn(v.x, bv[j]), 0.0f);
            v1[j] = fmaxf(__fadd_rn(v.y, bv[j]), 0.0f);
        }
        size_t base0 = (size_t)(m0 + lm) * N + n0 + tx * 4;
        *(float4*)&C[base0]     = make_float4(v0[0], v0[1], v0[2], v0[3]);
        *(float4*)&C[base0 + N] = make_float4(v1[0], v1[1], v1[2], v1[3]);
    }
}

// ---------------- GRU fuse (float4) ----------------
__global__ void gru_fuse() {
    int i = blockIdx.x * blockDim.x + threadIdx.x;
    if (i >= BB * HH / 4) return;
    int b = i >> 7, j = (i & 127) * 4;
    const float* gx = g_buf + OFF_GX + (size_t)b * G3;
    const float* gh = g_buf + OFF_GH + (size_t)b * G3;
    float4 xr = *(const float4*)&gx[j];
    float4 xz = *(const float4*)&gx[HH + j];
    float4 xn = *(const float4*)&gx[2 * HH + j];
    float4 hr = *(const float4*)&gh[j];
    float4 hz = *(const float4*)&gh[HH + j];
    float4 hn = *(const float4*)&gh[2 * HH + j];
    float4 hv = *(const float4*)&g_buf[OFF_H + b * HH + j];
    float4 o;
    {
        float r = sigf(__fadd_rn(xr.x, hr.x));
        float zg = sigf(__fadd_rn(xz.x, hz.x));
        float n = tanhf(__fadd_rn(xn.x, __fmul_rn(r, hn.x)));
        o.x = __fadd_rn(__fmul_rn(__fsub_rn(1.0f, zg), n), __fmul_rn(zg, hv.x));
    }
    {
        float r = sigf(__fadd_rn(xr.y, hr.y));
        float zg = sigf(__fadd_rn(xz.y, hz.y));
        float n = tanhf(__fadd_rn(xn.y, __fmul_rn(r, hn.y)));
        o.y = __fadd_rn(__fmul_rn(__fsub_rn(1.0f, zg), n), __fmul_rn(zg, hv.y));
    }
    {
        float r = sigf(__fadd_rn(xr.z, hr.z));
        float zg = sigf(__fadd_rn(xz.z, hz.z));
        float n = tanhf(__fadd_rn(xn.z, __fmul_rn(r, hn.z)));
        o.z = __fadd_rn(__fmul_rn(__fsub_rn(1.0f, zg), n), __fmul_rn(zg, hv.z));
    }
    {
        float r = sigf(__fadd_rn(xr.w, hr.w));
        float zg = sigf(__fadd_rn(xz.w, hz.w));
        float n = tanhf(__fadd_rn(xn.w, __fmul_rn(r, hn.w)));
        o.w = __fadd_rn(__fmul_rn(__fsub_rn(1.0f, zg), n), __fmul_rn(zg, hv.w));
    }
    *(float4*)&g_buf[OFF_H + b * HH + j] = o;
}

// ---------------- post-VQ (also resets dmin/zz for next step) ----------------
__global__ void postvq(float* __restrict__ out, int t) {
    int b = blockIdx.x, d = threadIdx.x;
    unsigned idx = (unsigned)(((ull*)(g_buf + OFF_DMIN))[b] & 0xFFFFFFFFULL);
    float zv = g_buf[OFF_Z + b * DD + d];
    float zq = g_buf[OFF_CB + (size_t)idx * DD + d];
    float ste = __fadd_rn(zv, __fsub_rn(zq, zv));
    out[OUT_CODES + ((size_t)b * TT + t) * DD + d] = ste;
    out[OUT_ZC + ((size_t)b * TT + t) * DD + d] = zv;
    g_buf[OFF_PREV + b * DD + d] = ste;
    if (d == 0) {
        out[OUT_IDX + b * TT + t] = (float)idx;
        atomicAdd(&g_buf[OFF_COUNTS + idx], 1.0f);
    }
    atomicAdd(&g_buf[OFF_DW + (size_t)idx * DD + d], zv);
    float diff = __fsub_rn(zv, zq);
    __shared__ float sred[256];
    sred[d] = __fmul_rn(diff, diff);
    __syncthreads();
    #pragma unroll
    for (int o = 128; o; o >>= 1) {
        if (d < o) sred[d] = __fadd_rn(sred[d], sred[d + o]);
        __syncthreads();
    }
    if (d == 0) {
        atomicAdd(&g_buf[OFF_LOSS], sred[0]);
        ((ull*)(g_buf + OFF_DMIN))[b] = 0xFFFFFFFFFFFFFFFFULL;
        g_buf[OFF_ZZ + b] = 0.0f;
    }
}

// ---------------- EMA update (analytic n_tot) ----------------
__global__ void ema_c(float nt) {
    int k = blockIdx.x, d = threadIdx.x;
    float csv = __fadd_rn(__fmul_rn(0.99f, g_buf[OFF_CS + k]),
                          __fmul_rn(0.01f, g_buf[OFF_COUNTS + k]));
    float s = __fmul_rn(__fdiv_rn(__fadd_rn(csv, 1e-5f),
                                  __fadd_rn(nt, 0.08192f)), nt);
    int i = k * DD + d;
    float e = __fadd_rn(__fmul_rn(0.99f, g_buf[OFF_EW + i]),
                        __fmul_rn(0.01f, g_buf[OFF_DW + i]));
    g_buf[OFF_EW + i] = e;
    float cbv = __fdiv_rn(e, s);
    g_buf[OFF_CB + i] = cbv;
    g_buf[OFF_DW + i] = 0.0f;
    __shared__ float sr[256];
    sr[d] = __fmul_rn(cbv, cbv);
    __syncthreads();
    #pragma unroll
    for (int o = 128; o; o >>= 1) {
        if (d < o) sr[d] = __fadd_rn(sr[d], sr[d + o]);
        __syncthreads();
    }
    if (d == 0) {
        g_buf[OFF_CBSQ + k] = sr[0];
        g_buf[OFF_CS + k] = s;
        g_buf[OFF_COUNTS + k] = 0.0f;
    }
}

// ---------------- finalize ----------------
__global__ void write_h(float* __restrict__ out) {
    int i = blockIdx.x * blockDim.x + threadIdx.x;
    if (i < BB * HH) out[OUT_H + i] = g_buf[OFF_H + i];
    if (i == 0)
        out[OUT_LOSS] = 0.25f * (g_buf[OFF_LOSS] / 262144.0f) * 0.125f;
}

// ---------------- launch ----------------
extern "C" void kernel_launch(void* const* d_in, const int* in_sizes, int n_in,
                              void* d_out, int out_size) {
    const float* sf   = (const float*)d_in[0];
    const float* bos  = (const float*)d_in[1];
    const float* W_ih = (const float*)d_in[2];
    const float* W_hh = (const float*)d_in[3];
    const float* b_ih = (const float*)d_in[4];
    const float* b_hh = (const float*)d_in[5];
    const float* Wg   = (const float*)d_in[6];
    const float* bg   = (const float*)d_in[7];
    const float* Wb   = (const float*)d_in[8];
    const float* bb   = (const float*)d_in[9];
    const float* W1   = (const float*)d_in[10];
    const float* b1   = (const float*)d_in[11];
    const float* W2   = (const float*)d_in[12];
    const float* b2   = (const float*)d_in[13];
    const float* cb_in = (const float*)d_in[14];
    const float* cs_in = (const float*)d_in[15];
    const float* ew_in = (const float*)d_in[16];
    float* out = (float*)d_out;

    void* sym = nullptr;
    cudaGetSymbolAddress(&sym, g_buf);
    float* g = (float*)sym;

    float ntf[TT];
    {
        double S = 0.0;
        double dec = (double)0.99f;
        double add = 1024.0 * (double)0.01f;
        for (int t = 0; t < TT; t++) { S = dec * S + add; ntf[t] = (float)S; }
    }

    init_copy<<<(KK * DD + 255) / 256, 256>>>(cb_in, cs_in, ew_in);
    init_state<<<(BB * HH + 255) / 256, 256>>>(bos);
    packw<<<(CC * HH + 255) / 256, 256>>>(Wg, bg, Wb, bb);
    smean_kernel<<<(BB * CC / 4 * 32 + 255) / 256, 256>>>(sf);
    cbsq_init<<<KK, 256>>>();

    for (int t = 0; t < TT; t++) {
        gru_gemm<<<dim3(G3 / 64, BB / 128, 2), 256>>>(W_ih, b_ih, W_hh, b_hh);
        gru_fuse<<<(BB * HH / 4 + 255) / 256, 256>>>();
        med_gemm<0, 0><<<dim3(1024 / 64, BB / 64), 128>>>(g + OFF_H, g + OFF_WGB, g + OFF_BGB, g + OFF_GB, 1024, HH);
        pin_gemm<<<dim3(HH / 64, BB / 64), 128>>>(W1, b1, g + OFF_Z1);
        med_gemm<0, 1><<<dim3(DD / 64, BB / 64), 128>>>(g + OFF_Z1, W2, b2, g + OFF_Z, DD, HH);
        vq_gemm<<<dim3(KK / 64, BB / 128), 256>>>();
        postvq<<<BB, 256>>>(out, t);
        ema_c<<<KK, 256>>>(ntf[t]);
    }

    write_h<<<(BB * HH + 255) / 256, 256>>>(out);
    (void)in_sizes; (void)n_in; (void)out_size;
}